// round 16
// baseline (speedup 1.0000x reference)
#include <cuda_runtime.h>
#include <cuda_fp16.h>
#include <math.h>

#define NB    4
#define NN    1000
#define NT    8
#define NF    64
#define NH    64
#define NHEAD 4
#define NE    16000
#define NG    32
#define GN    32000
#define BN    4000
#define TOTE  512000
#define NEG_SLOPE 0.2f

typedef unsigned long long u64;

// -------------------- scratch ------------------------------------------------
__device__ __half2 g_hfeat16[GN * 128];   // h = in @ W, fp16 pairs [node][128]
__device__ float g_asrc[GN * 4];
__device__ float g_adst[GN * 4];
__device__ float g_gat1[GN * 64];
__device__ float g_gat2[GN * 64];
__device__ float g_gi[NT * BN * 192];
__device__ int   g_offs[GN + 1];
__device__ int   g_srclist[TOTE];
// transposed weights [k][j]
__device__ float g_whh0T[64 * 192];
__device__ float g_wih1T[64 * 192];
__device__ float g_whh1T[64 * 192];
__device__ float g_wih0T[64 * 192];

// -------------------- fast math ----------------------------------------------
__device__ __forceinline__ float leaky(float x) { return fmaxf(x, NEG_SLOPE * x); }
__device__ __forceinline__ float fsig(float x) {
    float e = __expf(-fabsf(x));
    float r = __fdividef(1.f, 1.f + e);
    return x >= 0.f ? r : r * e;
}
__device__ __forceinline__ float ftanh(float x) {
    float e = __expf(-2.f * fabsf(x));
    float t = 1.f - __fdividef(2.f * e, 1.f + e);
    return x >= 0.f ? t : -t;
}
// packed f32x2 helpers
__device__ __forceinline__ u64 pk2(float a) {
    u64 r; asm("mov.b64 %0, {%1, %1};" : "=l"(r) : "f"(a)); return r;
}
__device__ __forceinline__ float2 u2f(u64 v) { return *(float2*)&v; }
__device__ __forceinline__ u64 ffma2(u64 a, u64 b, u64 c) {
    u64 d; asm("fma.rn.f32x2 %0, %1, %2, %3;" : "=l"(d) : "l"(a), "l"(b), "l"(c));
    return d;
}

// -------------------- weight transpose ------------------------------------------
__global__ void wtrans_kernel(const float* __restrict__ Whh0,
                              const float* __restrict__ Wih1,
                              const float* __restrict__ Whh1,
                              const float* __restrict__ Wih0) {
    int i = blockIdx.x * blockDim.x + threadIdx.x;
    if (i >= 12288) return;
    int j = i / 64, k = i % 64;
    g_whh0T[k * 192 + j] = Whh0[i];
    g_wih1T[k * 192 + j] = Wih1[i];
    g_whh1T[k * 192 + j] = Whh1[i];
    g_wih0T[k * 192 + j] = Wih0[i];
}

// -------------------- fused CSR build: hist + scan + scatter per graph ----------
__global__ __launch_bounds__(1024)
void csr_kernel(const int* __restrict__ ei) {
    __shared__ int sdeg[NN];
    __shared__ int wsum[32];
    int g = blockIdx.x;
    int tid = threadIdx.x, lane = tid & 31, wid = tid >> 5;
    const int* srcp = &ei[(g * 2 + 0) * NE];
    const int* dstp = &ei[(g * 2 + 1) * NE];

    if (tid < NN) sdeg[tid] = 0;
    __syncthreads();

    for (int e4 = tid; e4 < NE / 4; e4 += 1024) {
        int4 d = __ldg((const int4*)&dstp[e4 * 4]);
        atomicAdd(&sdeg[d.x], 1);
        atomicAdd(&sdeg[d.y], 1);
        atomicAdd(&sdeg[d.z], 1);
        atomicAdd(&sdeg[d.w], 1);
    }
    __syncthreads();

    int d = (tid < NN) ? sdeg[tid] : 0;
    int s = d;
#pragma unroll
    for (int o = 1; o < 32; o <<= 1) {
        int v = __shfl_up_sync(0xffffffffu, s, o);
        if (lane >= o) s += v;
    }
    if (lane == 31) wsum[wid] = s;
    __syncthreads();
    if (wid == 0) {
        int v = wsum[lane];
#pragma unroll
        for (int o = 1; o < 32; o <<= 1) {
            int u = __shfl_up_sync(0xffffffffu, v, o);
            if (lane >= o) v += u;
        }
        wsum[lane] = v;
    }
    __syncthreads();
    int excl = s - d + (wid > 0 ? wsum[wid - 1] : 0);
    __syncthreads();
    if (tid < NN) {
        g_offs[g * NN + tid] = g * NE + excl;
        sdeg[tid] = excl;
    }
    if (g == 0 && tid == 0) g_offs[GN] = TOTE;
    __syncthreads();

    int base = g * NE;
    for (int e4 = tid; e4 < NE / 4; e4 += 1024) {
        int4 sv = __ldg((const int4*)&srcp[e4 * 4]);
        int4 dv = __ldg((const int4*)&dstp[e4 * 4]);
        int p;
        p = atomicAdd(&sdeg[dv.x], 1); g_srclist[base + p] = sv.x;
        p = atomicAdd(&sdeg[dv.y], 1); g_srclist[base + p] = sv.y;
        p = atomicAdd(&sdeg[dv.z], 1); g_srclist[base + p] = sv.z;
        p = atomicAdd(&sdeg[dv.w], 1); g_srclist[base + p] = sv.w;
    }
}

// -------------------- GAT prologue (FFMA2) + attention scalars -------------------
__global__ __launch_bounds__(256)
void prologue_kernel(const float* __restrict__ in, const float* __restrict__ W,
                     const float* __restrict__ att_src, const float* __restrict__ att_dst,
                     int mode) {
    __shared__ float xsT[64 * 36];
    int t = threadIdx.x;
    int cq = t & 63, rq = t >> 6;
    int lane = t & 31;
    int nodebase = blockIdx.x * 32;

    for (int linear = t; linear < 2048; linear += 256) {
        int r = linear >> 6, k = linear & 63;
        int node = nodebase + r;
        float v;
        if (mode == 0) {
            int gg = node / NN, n = node % NN;
            int b = gg >> 3, tt = gg & 7;
            v = in[((b * NN + n) * NT + tt) * NF + k];
        } else {
            v = g_gat1[node * 64 + k];
        }
        xsT[k * 36 + r] = v;
    }
    __syncthreads();

    const float4* Wv = (const float4*)W;
    u64 acc[4][4];   // [rowpair][col]
#pragma unroll
    for (int p = 0; p < 4; p++)
#pragma unroll
        for (int c = 0; c < 4; c++) acc[p][c] = 0ull;

    int rbase = rq * 8;
    for (int k = 0; k < 64; k++) {
        float4 w = __ldg(&Wv[k * 64 + cq]);
        u64 w0 = pk2(w.x), w1 = pk2(w.y), w2 = pk2(w.z), w3 = pk2(w.w);
        const u64* xp = (const u64*)&xsT[k * 36 + rbase];
#pragma unroll
        for (int p = 0; p < 4; p++) {
            u64 xv = xp[p];
            acc[p][0] = ffma2(xv, w0, acc[p][0]);
            acc[p][1] = ffma2(xv, w1, acc[p][1]);
            acc[p][2] = ffma2(xv, w2, acc[p][2]);
            acc[p][3] = ffma2(xv, w3, acc[p][3]);
        }
    }

    float4 as4 = __ldg((const float4*)&att_src[cq * 4]);
    float4 ad4 = __ldg((const float4*)&att_dst[cq * 4]);
    int hd = cq >> 4;

#pragma unroll
    for (int i = 0; i < 8; i++) {
        int p = i >> 1, e = i & 1;
        float2 c0 = u2f(acc[p][0]), c1 = u2f(acc[p][1]);
        float2 c2 = u2f(acc[p][2]), c3 = u2f(acc[p][3]);
        float4 a = e ? make_float4(c0.y, c1.y, c2.y, c3.y)
                     : make_float4(c0.x, c1.x, c2.x, c3.x);
        int node = nodebase + rbase + i;

        __half2 h0 = __floats2half2_rn(a.x, a.y);
        __half2 h1 = __floats2half2_rn(a.z, a.w);
        uint2 u;
        u.x = *(unsigned*)&h0;
        u.y = *(unsigned*)&h1;
        *(uint2*)&g_hfeat16[node * 128 + cq * 2] = u;

        float ps = a.x * as4.x + a.y * as4.y + a.z * as4.z + a.w * as4.w;
        float pd = a.x * ad4.x + a.y * ad4.y + a.z * ad4.z + a.w * ad4.w;
#pragma unroll
        for (int o = 8; o; o >>= 1) {
            ps += __shfl_xor_sync(0xffffffffu, ps, o);
            pd += __shfl_xor_sync(0xffffffffu, pd, o);
        }
        if ((lane & 15) == 0) {
            g_asrc[node * 4 + hd] = ps;
            g_adst[node * 4 + hd] = pd;
        }
    }
}

// -------------------- GAT aggregation: warp/node, prefetch-pipelined -------------
__global__ __launch_bounds__(256)
void aggregate_kernel(const float* __restrict__ bias, int relu_flag, int which) {
    int node = blockIdx.x * 8 + (threadIdx.x >> 5);
    int lane = threadIdx.x & 31;
    int g = node / NN;
    int gbase = g * NN;
    int off = g_offs[node];
    int deg = g_offs[node + 1] - off;

    int eh_e = lane >> 2, eh_h = lane & 3;
    int fh = lane >> 3;

    float4 ad4 = *(const float4*)&g_adst[node * 4];
    float4 asn = *(const float4*)&g_asrc[node * 4];
    float adh_w = ((const float*)&ad4)[eh_h];
    float w_self = __expf(leaky(((const float*)&asn)[fh] + ((const float*)&ad4)[fh]));

    float acc[8];
    {
        uint4 raw = *(const uint4*)&g_hfeat16[node * 128 + lane * 4];
        const __half2* hp = (const __half2*)&raw;
        float2 f0 = __half22float2(hp[0]), f1 = __half22float2(hp[1]);
        float2 f2 = __half22float2(hp[2]), f3 = __half22float2(hp[3]);
        acc[0] = w_self * f0.x; acc[1] = w_self * f0.y;
        acc[2] = w_self * f1.x; acc[3] = w_self * f1.y;
        acc[4] = w_self * f2.x; acc[5] = w_self * f2.y;
        acc[6] = w_self * f3.x; acc[7] = w_self * f3.y;
    }

    float s_part = 0.f;
    int nfull = deg & ~7;

    for (int base = 0; base < nfull; base += 8) {
        int src = g_srclist[off + base + eh_e];
        int sg = gbase + src;
        float w = __expf(leaky(__ldg(&g_asrc[sg * 4 + eh_h]) + adh_w));
        s_part += w;

        int sj0 = __shfl_sync(0xffffffffu, sg, 0);
        float wv = __shfl_sync(0xffffffffu, w, fh);
        uint4 raw = __ldg((const uint4*)&g_hfeat16[sj0 * 128 + lane * 4]);
#pragma unroll
        for (int j = 0; j < 8; j++) {
            uint4 rawn;
            float wvn;
            if (j < 7) {
                int sjn = __shfl_sync(0xffffffffu, sg, (j + 1) * 4);
                wvn = __shfl_sync(0xffffffffu, w, (j + 1) * 4 + fh);
                rawn = __ldg((const uint4*)&g_hfeat16[sjn * 128 + lane * 4]);
            }
            const __half2* hp = (const __half2*)&raw;
            float2 f0 = __half22float2(hp[0]), f1 = __half22float2(hp[1]);
            float2 f2 = __half22float2(hp[2]), f3 = __half22float2(hp[3]);
            acc[0] += wv * f0.x; acc[1] += wv * f0.y;
            acc[2] += wv * f1.x; acc[3] += wv * f1.y;
            acc[4] += wv * f2.x; acc[5] += wv * f2.y;
            acc[6] += wv * f3.x; acc[7] += wv * f3.y;
            if (j < 7) { raw = rawn; wv = wvn; }
        }
    }

    int rem = deg - nfull;
    if (rem) {
        bool valid = eh_e < rem;
        int src = g_srclist[off + nfull + (valid ? eh_e : 0)];
        int sg = gbase + src;
        float w = valid ? __expf(leaky(__ldg(&g_asrc[sg * 4 + eh_h]) + adh_w)) : 0.f;
        s_part += w;
        for (int j = 0; j < rem; j++) {
            int sj = __shfl_sync(0xffffffffu, sg, j * 4);
            float wv = __shfl_sync(0xffffffffu, w, j * 4 + fh);
            uint4 raw = __ldg((const uint4*)&g_hfeat16[sj * 128 + lane * 4]);
            const __half2* hp = (const __half2*)&raw;
            float2 f0 = __half22float2(hp[0]), f1 = __half22float2(hp[1]);
            float2 f2 = __half22float2(hp[2]), f3 = __half22float2(hp[3]);
            acc[0] += wv * f0.x; acc[1] += wv * f0.y;
            acc[2] += wv * f1.x; acc[3] += wv * f1.y;
            acc[4] += wv * f2.x; acc[5] += wv * f2.y;
            acc[6] += wv * f3.x; acc[7] += wv * f3.y;
        }
    }

    s_part += __shfl_xor_sync(0xffffffffu, s_part, 4);
    s_part += __shfl_xor_sync(0xffffffffu, s_part, 8);
    s_part += __shfl_xor_sync(0xffffffffu, s_part, 16);
    float s_tot = __shfl_sync(0xffffffffu, s_part, fh) + w_self;
    float inv = __fdividef(1.f, s_tot);
#pragma unroll
    for (int i = 0; i < 8; i++) acc[i] *= inv;

#pragma unroll
    for (int i = 0; i < 8; i++) {
        acc[i] += __shfl_xor_sync(0xffffffffu, acc[i], 8);
        acc[i] += __shfl_xor_sync(0xffffffffu, acc[i], 16);
    }

    if (lane < 8) {
        float4 b0 = __ldg((const float4*)&bias[lane * 8]);
        float4 b1 = __ldg((const float4*)&bias[lane * 8 + 4]);
        float4 o0, o1;
        o0.x = acc[0] * 0.25f + b0.x; o0.y = acc[1] * 0.25f + b0.y;
        o0.z = acc[2] * 0.25f + b0.z; o0.w = acc[3] * 0.25f + b0.w;
        o1.x = acc[4] * 0.25f + b1.x; o1.y = acc[5] * 0.25f + b1.y;
        o1.z = acc[6] * 0.25f + b1.z; o1.w = acc[7] * 0.25f + b1.w;
        if (relu_flag) {
            o0.x = fmaxf(o0.x, 0.f); o0.y = fmaxf(o0.y, 0.f);
            o0.z = fmaxf(o0.z, 0.f); o0.w = fmaxf(o0.w, 0.f);
            o1.x = fmaxf(o1.x, 0.f); o1.y = fmaxf(o1.y, 0.f);
            o1.z = fmaxf(o1.z, 0.f); o1.w = fmaxf(o1.w, 0.f);
        }
        float* dst = (which == 0) ? g_gat1 : g_gat2;
        *(float4*)&dst[node * 64 + lane * 8] = o0;
        *(float4*)&dst[node * 64 + lane * 8 + 4] = o1;
    }
}

// -------------------- GRU input matmul (FFMA2, all t), 32-row tiles --------------
__global__ __launch_bounds__(192)
void gi_kernel(const float* __restrict__ bih0) {
    __shared__ float xsT[64 * 36];
    int t = threadIdx.x;
    int cq = t % 48, rq = t / 48;
    int rowbase = blockIdx.x * 32;

    for (int linear = t; linear < 2048; linear += 192) {
        int r = linear >> 6, k = linear & 63;
        int row = rowbase + r;
        int tt = row / BN, bn = row % BN;
        int b = bn / NN, n = bn % NN;
        xsT[k * 36 + r] = g_gat2[((b * NT + tt) * NN + n) * 64 + k];
    }
    __syncthreads();

    const float4* Wv = (const float4*)g_wih0T;
    u64 acc[4][4];
#pragma unroll
    for (int p = 0; p < 4; p++)
#pragma unroll
        for (int c = 0; c < 4; c++) acc[p][c] = 0ull;
    int rbase = rq * 8;
    for (int k = 0; k < 64; k++) {
        float4 w = __ldg(&Wv[k * 48 + cq]);
        u64 w0 = pk2(w.x), w1 = pk2(w.y), w2 = pk2(w.z), w3 = pk2(w.w);
        const u64* xp = (const u64*)&xsT[k * 36 + rbase];
#pragma unroll
        for (int p = 0; p < 4; p++) {
            u64 xv = xp[p];
            acc[p][0] = ffma2(xv, w0, acc[p][0]);
            acc[p][1] = ffma2(xv, w1, acc[p][1]);
            acc[p][2] = ffma2(xv, w2, acc[p][2]);
            acc[p][3] = ffma2(xv, w3, acc[p][3]);
        }
    }
    float4 bj = __ldg((const float4*)&bih0[cq * 4]);
#pragma unroll
    for (int i = 0; i < 8; i++) {
        int p = i >> 1, e = i & 1;
        float2 c0 = u2f(acc[p][0]), c1 = u2f(acc[p][1]);
        float2 c2 = u2f(acc[p][2]), c3 = u2f(acc[p][3]);
        float4 v = e ? make_float4(c0.y + bj.x, c1.y + bj.y, c2.y + bj.z, c3.y + bj.w)
                     : make_float4(c0.x + bj.x, c1.x + bj.y, c2.x + bj.z, c3.x + bj.w);
        *(float4*)&g_gi[(rowbase + rbase + i) * 192 + cq * 4] = v;
    }
}

// -------------------- fused GRU (FFMA2 col-pairs): all 8 steps + head MLP --------
__global__ __launch_bounds__(192)
void gru_fused_kernel(const float* __restrict__ bhh0,
                      const float* __restrict__ bih1, const float* __restrict__ bhh1,
                      const float* __restrict__ pW1, const float* __restrict__ pb1,
                      const float* __restrict__ pW2, const float* __restrict__ pb2,
                      float* __restrict__ out) {
    const int R = 8;
    __shared__ float h1T[64 * 10];
    __shared__ float h2T[64 * 10];
    __shared__ float st[R * 196];
    __shared__ float st2[R * 64];

    int tid = threadIdx.x;
    int cq = tid % 48, rq = tid / 48;
    int rowbase = blockIdx.x * R;
    int cbase = cq * 4;
    int gate = cq >> 4;
    int rb = rq * 2;

    for (int idx = tid; idx < 64 * 10; idx += 192) {
        h1T[idx] = 0.f;
        h2T[idx] = 0.f;
    }

    float4 vbhh0 = __ldg((const float4*)&bhh0[cbase]);
    float4 vbih1 = __ldg((const float4*)&bih1[cbase]);
    float4 vbhh1 = __ldg((const float4*)&bhh1[cbase]);

    // row stride: 192 floats = 48 ulonglong2 groups per k
    const ulonglong2* W0u  = (const ulonglong2*)g_whh0T;
    const ulonglong2* Wi1u = (const ulonglong2*)g_wih1T;
    const ulonglong2* Wh1u = (const ulonglong2*)g_whh1T;

    for (int t = 0; t < NT; t++) {
        // prefetch gate inputs for this step BEFORE the barrier + matmul
        int gib = (t * BN + rowbase + rb) * 192 + cbase;
        float4 gi0 = __ldg((const float4*)&g_gi[gib]);
        float4 gi1 = __ldg((const float4*)&g_gi[gib + 192]);

        __syncthreads();
        {
            // acc[row][colpair]: u64 = (c0,c1) or (c2,c3)
            u64 a00 = 0ull, a01 = 0ull, a10 = 0ull, a11 = 0ull;
            for (int k = 0; k < 64; k++) {
                ulonglong2 w = __ldg(&W0u[k * 48 + cq]);   // LDG.128: (w0,w1),(w2,w3)
                float2 h = *(const float2*)&h1T[k * 10 + rb];
                u64 h0 = pk2(h.x), h1 = pk2(h.y);
                a00 = ffma2(h0, w.x, a00);
                a01 = ffma2(h0, w.y, a01);
                a10 = ffma2(h1, w.x, a10);
                a11 = ffma2(h1, w.y, a11);
            }
#pragma unroll
            for (int i = 0; i < 2; i++) {
                int r = rb + i;
                float4 gi = (i == 0) ? gi0 : gi1;
                float2 p0 = u2f(i ? a10 : a00);
                float2 p1 = u2f(i ? a11 : a01);
                float4 gh;
                gh.x = p0.x + vbhh0.x; gh.y = p0.y + vbhh0.y;
                gh.z = p1.x + vbhh0.z; gh.w = p1.y + vbhh0.w;
                if (gate < 2) {
                    float4 v = make_float4(gi.x + gh.x, gi.y + gh.y, gi.z + gh.z, gi.w + gh.w);
                    *(float4*)&st[r * 196 + cbase] = v;
                } else {
                    *(float4*)&st[r * 196 + cbase] = gi;
                    *(float4*)&st2[r * 64 + (cbase - 128)] = gh;
                }
            }
        }
        __syncthreads();

        for (int idx = tid; idx < R * 64; idx += 192) {
            int r = idx >> 6, c = idx & 63;
            float rg = fsig(st[r * 196 + c]);
            float zg = fsig(st[r * 196 + 64 + c]);
            float nv = ftanh(st[r * 196 + 128 + c] + rg * st2[r * 64 + c]);
            float h1o = h1T[c * 10 + r];
            h1T[c * 10 + r] = (1.f - zg) * nv + zg * h1o;
        }
        __syncthreads();

        {
            u64 i00 = 0ull, i01 = 0ull, i10 = 0ull, i11 = 0ull;
            u64 h00 = 0ull, h01 = 0ull, h10 = 0ull, h11 = 0ull;
            for (int k = 0; k < 64; k++) {
                ulonglong2 wi = __ldg(&Wi1u[k * 48 + cq]);
                ulonglong2 wh = __ldg(&Wh1u[k * 48 + cq]);
                float2 a = *(const float2*)&h1T[k * 10 + rb];
                float2 b = *(const float2*)&h2T[k * 10 + rb];
                u64 a0 = pk2(a.x), a1 = pk2(a.y);
                u64 b0 = pk2(b.x), b1 = pk2(b.y);
                i00 = ffma2(a0, wi.x, i00);
                i01 = ffma2(a0, wi.y, i01);
                i10 = ffma2(a1, wi.x, i10);
                i11 = ffma2(a1, wi.y, i11);
                h00 = ffma2(b0, wh.x, h00);
                h01 = ffma2(b0, wh.y, h01);
                h10 = ffma2(b1, wh.x, h10);
                h11 = ffma2(b1, wh.y, h11);
            }
#pragma unroll
            for (int i = 0; i < 2; i++) {
                int r = rb + i;
                float2 ip0 = u2f(i ? i10 : i00);
                float2 ip1 = u2f(i ? i11 : i01);
                float2 hp0 = u2f(i ? h10 : h00);
                float2 hp1 = u2f(i ? h11 : h01);
                float4 gi, gh;
                gi.x = ip0.x + vbih1.x; gi.y = ip0.y + vbih1.y;
                gi.z = ip1.x + vbih1.z; gi.w = ip1.y + vbih1.w;
                gh.x = hp0.x + vbhh1.x; gh.y = hp0.y + vbhh1.y;
                gh.z = hp1.x + vbhh1.z; gh.w = hp1.y + vbhh1.w;
                if (gate < 2) {
                    float4 v = make_float4(gi.x + gh.x, gi.y + gh.y, gi.z + gh.z, gi.w + gh.w);
                    *(float4*)&st[r * 196 + cbase] = v;
                } else {
                    *(float4*)&st[r * 196 + cbase] = gi;
                    *(float4*)&st2[r * 64 + (cbase - 128)] = gh;
                }
            }
        }
        __syncthreads();

        for (int idx = tid; idx < R * 64; idx += 192) {
            int r = idx >> 6, c = idx & 63;
            float rg = fsig(st[r * 196 + c]);
            float zg = fsig(st[r * 196 + 64 + c]);
            float nv = ftanh(st[r * 196 + 128 + c] + rg * st2[r * 64 + c]);
            float h2o = h2T[c * 10 + r];
            h2T[c * 10 + r] = (1.f - zg) * nv + zg * h2o;
        }
    }
    __syncthreads();

    // head MLP: 128 threads, 2 row-groups of 4
    if (tid < 128) {
        int j = tid & 63, rh = tid >> 6;
#pragma unroll
        for (int rr = 0; rr < 4; rr++) {
            int r = rh * 4 + rr;
            float a = __ldg(&pb1[j]);
            for (int k = 0; k < 64; k++) a += h2T[k * 10 + r] * __ldg(&pW1[k * 64 + j]);
            st[r * 68 + j] = fmaxf(a, 0.f);
        }
    }
    __syncthreads();
    if (tid < 80) {
        int r = tid / 10, o = tid % 10;
        float a = __ldg(&pb2[o]);
        for (int k = 0; k < 64; k++) a += st[r * 68 + k] * __ldg(&pW2[k * 10 + o]);
        out[(rowbase + r) * 10 + o] = a;
    }
}

// -------------------- launch ------------------------------------------------------
extern "C" void kernel_launch(void* const* d_in, const int* in_sizes, int n_in,
                              void* d_out, int out_size) {
    const float* x    = (const float*)d_in[0];
    const int*   ei   = (const int*)  d_in[1];
    const float* W1   = (const float*)d_in[3];
    const float* as1  = (const float*)d_in[4];
    const float* ad1  = (const float*)d_in[5];
    const float* b1   = (const float*)d_in[6];
    const float* W2   = (const float*)d_in[7];
    const float* as2  = (const float*)d_in[8];
    const float* ad2  = (const float*)d_in[9];
    const float* b2   = (const float*)d_in[10];
    const float* Wih0 = (const float*)d_in[13];
    const float* Whh0 = (const float*)d_in[14];
    const float* bih0 = (const float*)d_in[15];
    const float* bhh0 = (const float*)d_in[16];
    const float* Wih1 = (const float*)d_in[17];
    const float* Whh1 = (const float*)d_in[18];
    const float* bih1 = (const float*)d_in[19];
    const float* bhh1 = (const float*)d_in[20];
    const float* pW1  = (const float*)d_in[21];
    const float* pb1  = (const float*)d_in[22];
    const float* pW2  = (const float*)d_in[23];
    const float* pb2  = (const float*)d_in[24];
    float* out = (float*)d_out;

    csr_kernel<<<NG, 1024>>>(ei);                                 // 1
    prologue_kernel<<<GN / 32, 256>>>(x, W1, as1, ad1, 0);        // 2
    aggregate_kernel<<<GN / 8, 256>>>(b1, 1, 0);                  // 3
    prologue_kernel<<<GN / 32, 256>>>(nullptr, W2, as2, ad2, 1);  // 4
    aggregate_kernel<<<GN / 8, 256>>>(b2, 0, 1);                  // 5
    wtrans_kernel<<<48, 256>>>(Whh0, Wih1, Whh1, Wih0);           // 6
    gi_kernel<<<(NT * BN) / 32, 192>>>(bih0);                     // 7
    gru_fused_kernel<<<BN / 8, 192>>>(bhh0, bih1, bhh1, pW1, pb1, pW2, pb2, out); // 8
}

// round 17
// speedup vs baseline: 1.0156x; 1.0156x over previous
#include <cuda_runtime.h>
#include <cuda_fp16.h>
#include <math.h>

#define NB    4
#define NN    1000
#define NT    8
#define NF    64
#define NH    64
#define NHEAD 4
#define NE    16000
#define NG    32
#define GN    32000
#define BN    4000
#define TOTE  512000
#define NEG_SLOPE 0.2f

typedef unsigned long long u64;

// -------------------- scratch ------------------------------------------------
__device__ __half2 g_hfeat16[GN * 128];   // h = in @ W, fp16 pairs [node][128]
__device__ float g_asrc[GN * 4];
__device__ float g_adst[GN * 4];
__device__ float g_gat1[GN * 64];
__device__ float g_gat2[GN * 64];
__device__ float g_gi[NT * BN * 192];
__device__ int   g_offs[GN + 1];
__device__ int   g_srclist[TOTE];
// transposed weights [k][j]
__device__ float g_whh0T[64 * 192];
__device__ float g_wih1T[64 * 192];
__device__ float g_whh1T[64 * 192];
__device__ float g_wih0T[64 * 192];

// -------------------- fast math ----------------------------------------------
__device__ __forceinline__ float leaky(float x) { return fmaxf(x, NEG_SLOPE * x); }
// single-MUFU tanh (sm_75+)
__device__ __forceinline__ float ftanh(float x) {
    float y; asm("tanh.approx.f32 %0, %1;" : "=f"(y) : "f"(x)); return y;
}
// sigmoid via tanh identity: 1 MUFU + 2 FMA
__device__ __forceinline__ float fsig(float x) {
    float y; asm("tanh.approx.f32 %0, %1;" : "=f"(y) : "f"(x * 0.5f));
    return fmaf(y, 0.5f, 0.5f);
}
// packed f32x2 helpers
__device__ __forceinline__ u64 pk2(float a) {
    u64 r; asm("mov.b64 %0, {%1, %1};" : "=l"(r) : "f"(a)); return r;
}
__device__ __forceinline__ float2 u2f(u64 v) { return *(float2*)&v; }
__device__ __forceinline__ u64 ffma2(u64 a, u64 b, u64 c) {
    u64 d; asm("fma.rn.f32x2 %0, %1, %2, %3;" : "=l"(d) : "l"(a), "l"(b), "l"(c));
    return d;
}

// -------------------- fused CSR build + weight transpose -------------------------
// blocks 0..31: per-graph CSR; blocks 32..35: GRU weight transpose.
__global__ __launch_bounds__(1024)
void csr_kernel(const int* __restrict__ ei,
                const float* __restrict__ Whh0, const float* __restrict__ Wih1,
                const float* __restrict__ Whh1, const float* __restrict__ Wih0) {
    if (blockIdx.x >= NG) {
        int base = (blockIdx.x - NG) * 1024 + threadIdx.x;
        for (int i = base; i < 12288; i += 4096) {
            int j = i / 64, k = i % 64;
            g_whh0T[k * 192 + j] = Whh0[i];
            g_wih1T[k * 192 + j] = Wih1[i];
            g_whh1T[k * 192 + j] = Whh1[i];
            g_wih0T[k * 192 + j] = Wih0[i];
        }
        return;
    }

    __shared__ int sdeg[NN];
    __shared__ int wsum[32];
    int g = blockIdx.x;
    int tid = threadIdx.x, lane = tid & 31, wid = tid >> 5;
    const int* srcp = &ei[(g * 2 + 0) * NE];
    const int* dstp = &ei[(g * 2 + 1) * NE];

    if (tid < NN) sdeg[tid] = 0;
    __syncthreads();

    for (int e4 = tid; e4 < NE / 4; e4 += 1024) {
        int4 d = __ldg((const int4*)&dstp[e4 * 4]);
        atomicAdd(&sdeg[d.x], 1);
        atomicAdd(&sdeg[d.y], 1);
        atomicAdd(&sdeg[d.z], 1);
        atomicAdd(&sdeg[d.w], 1);
    }
    __syncthreads();

    int d = (tid < NN) ? sdeg[tid] : 0;
    int s = d;
#pragma unroll
    for (int o = 1; o < 32; o <<= 1) {
        int v = __shfl_up_sync(0xffffffffu, s, o);
        if (lane >= o) s += v;
    }
    if (lane == 31) wsum[wid] = s;
    __syncthreads();
    if (wid == 0) {
        int v = wsum[lane];
#pragma unroll
        for (int o = 1; o < 32; o <<= 1) {
            int u = __shfl_up_sync(0xffffffffu, v, o);
            if (lane >= o) v += u;
        }
        wsum[lane] = v;
    }
    __syncthreads();
    int excl = s - d + (wid > 0 ? wsum[wid - 1] : 0);
    __syncthreads();
    if (tid < NN) {
        g_offs[g * NN + tid] = g * NE + excl;
        sdeg[tid] = excl;
    }
    if (g == 0 && tid == 0) g_offs[GN] = TOTE;
    __syncthreads();

    int base = g * NE;
    for (int e4 = tid; e4 < NE / 4; e4 += 1024) {
        int4 sv = __ldg((const int4*)&srcp[e4 * 4]);
        int4 dv = __ldg((const int4*)&dstp[e4 * 4]);
        int p;
        p = atomicAdd(&sdeg[dv.x], 1); g_srclist[base + p] = sv.x;
        p = atomicAdd(&sdeg[dv.y], 1); g_srclist[base + p] = sv.y;
        p = atomicAdd(&sdeg[dv.z], 1); g_srclist[base + p] = sv.z;
        p = atomicAdd(&sdeg[dv.w], 1); g_srclist[base + p] = sv.w;
    }
}

// -------------------- GAT prologue (FFMA2) + attention scalars -------------------
__global__ __launch_bounds__(256)
void prologue_kernel(const float* __restrict__ in, const float* __restrict__ W,
                     const float* __restrict__ att_src, const float* __restrict__ att_dst,
                     int mode) {
    __shared__ float xsT[64 * 36];
    int t = threadIdx.x;
    int cq = t & 63, rq = t >> 6;
    int lane = t & 31;
    int nodebase = blockIdx.x * 32;

    for (int linear = t; linear < 2048; linear += 256) {
        int r = linear >> 6, k = linear & 63;
        int node = nodebase + r;
        float v;
        if (mode == 0) {
            int gg = node / NN, n = node % NN;
            int b = gg >> 3, tt = gg & 7;
            v = in[((b * NN + n) * NT + tt) * NF + k];
        } else {
            v = g_gat1[node * 64 + k];
        }
        xsT[k * 36 + r] = v;
    }
    __syncthreads();

    const float4* Wv = (const float4*)W;
    u64 acc[4][4];   // [rowpair][col]
#pragma unroll
    for (int p = 0; p < 4; p++)
#pragma unroll
        for (int c = 0; c < 4; c++) acc[p][c] = 0ull;

    int rbase = rq * 8;
    for (int k = 0; k < 64; k++) {
        float4 w = __ldg(&Wv[k * 64 + cq]);
        u64 w0 = pk2(w.x), w1 = pk2(w.y), w2 = pk2(w.z), w3 = pk2(w.w);
        const u64* xp = (const u64*)&xsT[k * 36 + rbase];
#pragma unroll
        for (int p = 0; p < 4; p++) {
            u64 xv = xp[p];
            acc[p][0] = ffma2(xv, w0, acc[p][0]);
            acc[p][1] = ffma2(xv, w1, acc[p][1]);
            acc[p][2] = ffma2(xv, w2, acc[p][2]);
            acc[p][3] = ffma2(xv, w3, acc[p][3]);
        }
    }

    float4 as4 = __ldg((const float4*)&att_src[cq * 4]);
    float4 ad4 = __ldg((const float4*)&att_dst[cq * 4]);
    int hd = cq >> 4;

#pragma unroll
    for (int i = 0; i < 8; i++) {
        int p = i >> 1, e = i & 1;
        float2 c0 = u2f(acc[p][0]), c1 = u2f(acc[p][1]);
        float2 c2 = u2f(acc[p][2]), c3 = u2f(acc[p][3]);
        float4 a = e ? make_float4(c0.y, c1.y, c2.y, c3.y)
                     : make_float4(c0.x, c1.x, c2.x, c3.x);
        int node = nodebase + rbase + i;

        __half2 h0 = __floats2half2_rn(a.x, a.y);
        __half2 h1 = __floats2half2_rn(a.z, a.w);
        uint2 u;
        u.x = *(unsigned*)&h0;
        u.y = *(unsigned*)&h1;
        *(uint2*)&g_hfeat16[node * 128 + cq * 2] = u;

        float ps = a.x * as4.x + a.y * as4.y + a.z * as4.z + a.w * as4.w;
        float pd = a.x * ad4.x + a.y * ad4.y + a.z * ad4.z + a.w * ad4.w;
#pragma unroll
        for (int o = 8; o; o >>= 1) {
            ps += __shfl_xor_sync(0xffffffffu, ps, o);
            pd += __shfl_xor_sync(0xffffffffu, pd, o);
        }
        if ((lane & 15) == 0) {
            g_asrc[node * 4 + hd] = ps;
            g_adst[node * 4 + hd] = pd;
        }
    }
}

// -------------------- GAT aggregation: warp/node, prefetch-pipelined -------------
__global__ __launch_bounds__(256)
void aggregate_kernel(const float* __restrict__ bias, int relu_flag, int which) {
    int node = blockIdx.x * 8 + (threadIdx.x >> 5);
    int lane = threadIdx.x & 31;
    int g = node / NN;
    int gbase = g * NN;
    int off = g_offs[node];
    int deg = g_offs[node + 1] - off;

    int eh_e = lane >> 2, eh_h = lane & 3;
    int fh = lane >> 3;

    float4 ad4 = *(const float4*)&g_adst[node * 4];
    float4 asn = *(const float4*)&g_asrc[node * 4];
    float adh_w = ((const float*)&ad4)[eh_h];
    float w_self = __expf(leaky(((const float*)&asn)[fh] + ((const float*)&ad4)[fh]));

    float acc[8];
    {
        uint4 raw = *(const uint4*)&g_hfeat16[node * 128 + lane * 4];
        const __half2* hp = (const __half2*)&raw;
        float2 f0 = __half22float2(hp[0]), f1 = __half22float2(hp[1]);
        float2 f2 = __half22float2(hp[2]), f3 = __half22float2(hp[3]);
        acc[0] = w_self * f0.x; acc[1] = w_self * f0.y;
        acc[2] = w_self * f1.x; acc[3] = w_self * f1.y;
        acc[4] = w_self * f2.x; acc[5] = w_self * f2.y;
        acc[6] = w_self * f3.x; acc[7] = w_self * f3.y;
    }

    float s_part = 0.f;
    int nfull = deg & ~7;

    for (int base = 0; base < nfull; base += 8) {
        int src = g_srclist[off + base + eh_e];
        int sg = gbase + src;
        float w = __expf(leaky(__ldg(&g_asrc[sg * 4 + eh_h]) + adh_w));
        s_part += w;

        int sj0 = __shfl_sync(0xffffffffu, sg, 0);
        float wv = __shfl_sync(0xffffffffu, w, fh);
        uint4 raw = __ldg((const uint4*)&g_hfeat16[sj0 * 128 + lane * 4]);
#pragma unroll
        for (int j = 0; j < 8; j++) {
            uint4 rawn;
            float wvn;
            if (j < 7) {
                int sjn = __shfl_sync(0xffffffffu, sg, (j + 1) * 4);
                wvn = __shfl_sync(0xffffffffu, w, (j + 1) * 4 + fh);
                rawn = __ldg((const uint4*)&g_hfeat16[sjn * 128 + lane * 4]);
            }
            const __half2* hp = (const __half2*)&raw;
            float2 f0 = __half22float2(hp[0]), f1 = __half22float2(hp[1]);
            float2 f2 = __half22float2(hp[2]), f3 = __half22float2(hp[3]);
            acc[0] += wv * f0.x; acc[1] += wv * f0.y;
            acc[2] += wv * f1.x; acc[3] += wv * f1.y;
            acc[4] += wv * f2.x; acc[5] += wv * f2.y;
            acc[6] += wv * f3.x; acc[7] += wv * f3.y;
            if (j < 7) { raw = rawn; wv = wvn; }
        }
    }

    int rem = deg - nfull;
    if (rem) {
        bool valid = eh_e < rem;
        int src = g_srclist[off + nfull + (valid ? eh_e : 0)];
        int sg = gbase + src;
        float w = valid ? __expf(leaky(__ldg(&g_asrc[sg * 4 + eh_h]) + adh_w)) : 0.f;
        s_part += w;
        for (int j = 0; j < rem; j++) {
            int sj = __shfl_sync(0xffffffffu, sg, j * 4);
            float wv = __shfl_sync(0xffffffffu, w, j * 4 + fh);
            uint4 raw = __ldg((const uint4*)&g_hfeat16[sj * 128 + lane * 4]);
            const __half2* hp = (const __half2*)&raw;
            float2 f0 = __half22float2(hp[0]), f1 = __half22float2(hp[1]);
            float2 f2 = __half22float2(hp[2]), f3 = __half22float2(hp[3]);
            acc[0] += wv * f0.x; acc[1] += wv * f0.y;
            acc[2] += wv * f1.x; acc[3] += wv * f1.y;
            acc[4] += wv * f2.x; acc[5] += wv * f2.y;
            acc[6] += wv * f3.x; acc[7] += wv * f3.y;
        }
    }

    s_part += __shfl_xor_sync(0xffffffffu, s_part, 4);
    s_part += __shfl_xor_sync(0xffffffffu, s_part, 8);
    s_part += __shfl_xor_sync(0xffffffffu, s_part, 16);
    float s_tot = __shfl_sync(0xffffffffu, s_part, fh) + w_self;
    float inv = __fdividef(1.f, s_tot);
#pragma unroll
    for (int i = 0; i < 8; i++) acc[i] *= inv;

#pragma unroll
    for (int i = 0; i < 8; i++) {
        acc[i] += __shfl_xor_sync(0xffffffffu, acc[i], 8);
        acc[i] += __shfl_xor_sync(0xffffffffu, acc[i], 16);
    }

    if (lane < 8) {
        float4 b0 = __ldg((const float4*)&bias[lane * 8]);
        float4 b1 = __ldg((const float4*)&bias[lane * 8 + 4]);
        float4 o0, o1;
        o0.x = acc[0] * 0.25f + b0.x; o0.y = acc[1] * 0.25f + b0.y;
        o0.z = acc[2] * 0.25f + b0.z; o0.w = acc[3] * 0.25f + b0.w;
        o1.x = acc[4] * 0.25f + b1.x; o1.y = acc[5] * 0.25f + b1.y;
        o1.z = acc[6] * 0.25f + b1.z; o1.w = acc[7] * 0.25f + b1.w;
        if (relu_flag) {
            o0.x = fmaxf(o0.x, 0.f); o0.y = fmaxf(o0.y, 0.f);
            o0.z = fmaxf(o0.z, 0.f); o0.w = fmaxf(o0.w, 0.f);
            o1.x = fmaxf(o1.x, 0.f); o1.y = fmaxf(o1.y, 0.f);
            o1.z = fmaxf(o1.z, 0.f); o1.w = fmaxf(o1.w, 0.f);
        }
        float* dst = (which == 0) ? g_gat1 : g_gat2;
        *(float4*)&dst[node * 64 + lane * 8] = o0;
        *(float4*)&dst[node * 64 + lane * 8 + 4] = o1;
    }
}

// -------------------- GRU input matmul (FFMA2, all t), 32-row tiles --------------
__global__ __launch_bounds__(192)
void gi_kernel(const float* __restrict__ bih0) {
    __shared__ float xsT[64 * 36];
    int t = threadIdx.x;
    int cq = t % 48, rq = t / 48;
    int rowbase = blockIdx.x * 32;

    for (int linear = t; linear < 2048; linear += 192) {
        int r = linear >> 6, k = linear & 63;
        int row = rowbase + r;
        int tt = row / BN, bn = row % BN;
        int b = bn / NN, n = bn % NN;
        xsT[k * 36 + r] = g_gat2[((b * NT + tt) * NN + n) * 64 + k];
    }
    __syncthreads();

    const float4* Wv = (const float4*)g_wih0T;
    u64 acc[4][4];
#pragma unroll
    for (int p = 0; p < 4; p++)
#pragma unroll
        for (int c = 0; c < 4; c++) acc[p][c] = 0ull;
    int rbase = rq * 8;
    for (int k = 0; k < 64; k++) {
        float4 w = __ldg(&Wv[k * 48 + cq]);
        u64 w0 = pk2(w.x), w1 = pk2(w.y), w2 = pk2(w.z), w3 = pk2(w.w);
        const u64* xp = (const u64*)&xsT[k * 36 + rbase];
#pragma unroll
        for (int p = 0; p < 4; p++) {
            u64 xv = xp[p];
            acc[p][0] = ffma2(xv, w0, acc[p][0]);
            acc[p][1] = ffma2(xv, w1, acc[p][1]);
            acc[p][2] = ffma2(xv, w2, acc[p][2]);
            acc[p][3] = ffma2(xv, w3, acc[p][3]);
        }
    }
    float4 bj = __ldg((const float4*)&bih0[cq * 4]);
#pragma unroll
    for (int i = 0; i < 8; i++) {
        int p = i >> 1, e = i & 1;
        float2 c0 = u2f(acc[p][0]), c1 = u2f(acc[p][1]);
        float2 c2 = u2f(acc[p][2]), c3 = u2f(acc[p][3]);
        float4 v = e ? make_float4(c0.y + bj.x, c1.y + bj.y, c2.y + bj.z, c3.y + bj.w)
                     : make_float4(c0.x + bj.x, c1.x + bj.y, c2.x + bj.z, c3.x + bj.w);
        *(float4*)&g_gi[(rowbase + rbase + i) * 192 + cq * 4] = v;
    }
}

// -------------------- fused GRU (FFMA2 col-pairs): all 8 steps + head MLP --------
__global__ __launch_bounds__(192)
void gru_fused_kernel(const float* __restrict__ bhh0,
                      const float* __restrict__ bih1, const float* __restrict__ bhh1,
                      const float* __restrict__ pW1, const float* __restrict__ pb1,
                      const float* __restrict__ pW2, const float* __restrict__ pb2,
                      float* __restrict__ out) {
    const int R = 8;
    __shared__ float h1T[64 * 10];
    __shared__ float h2T[64 * 10];
    __shared__ float st[R * 196];
    __shared__ float st2[R * 64];

    int tid = threadIdx.x;
    int cq = tid % 48, rq = tid / 48;
    int rowbase = blockIdx.x * R;
    int cbase = cq * 4;
    int gate = cq >> 4;
    int rb = rq * 2;

    for (int idx = tid; idx < 64 * 10; idx += 192) {
        h1T[idx] = 0.f;
        h2T[idx] = 0.f;
    }

    float4 vbhh0 = __ldg((const float4*)&bhh0[cbase]);
    float4 vbih1 = __ldg((const float4*)&bih1[cbase]);
    float4 vbhh1 = __ldg((const float4*)&bhh1[cbase]);

    // row stride: 192 floats = 48 ulonglong2 groups per k
    const ulonglong2* W0u  = (const ulonglong2*)g_whh0T;
    const ulonglong2* Wi1u = (const ulonglong2*)g_wih1T;
    const ulonglong2* Wh1u = (const ulonglong2*)g_whh1T;

    for (int t = 0; t < NT; t++) {
        int gib = (t * BN + rowbase + rb) * 192 + cbase;
        float4 gi0 = __ldg((const float4*)&g_gi[gib]);
        float4 gi1 = __ldg((const float4*)&g_gi[gib + 192]);

        __syncthreads();
        {
            u64 a00 = 0ull, a01 = 0ull, a10 = 0ull, a11 = 0ull;
            for (int k = 0; k < 64; k++) {
                ulonglong2 w = __ldg(&W0u[k * 48 + cq]);
                float2 h = *(const float2*)&h1T[k * 10 + rb];
                u64 h0 = pk2(h.x), h1 = pk2(h.y);
                a00 = ffma2(h0, w.x, a00);
                a01 = ffma2(h0, w.y, a01);
                a10 = ffma2(h1, w.x, a10);
                a11 = ffma2(h1, w.y, a11);
            }
#pragma unroll
            for (int i = 0; i < 2; i++) {
                int r = rb + i;
                float4 gi = (i == 0) ? gi0 : gi1;
                float2 p0 = u2f(i ? a10 : a00);
                float2 p1 = u2f(i ? a11 : a01);
                float4 gh;
                gh.x = p0.x + vbhh0.x; gh.y = p0.y + vbhh0.y;
                gh.z = p1.x + vbhh0.z; gh.w = p1.y + vbhh0.w;
                if (gate < 2) {
                    float4 v = make_float4(gi.x + gh.x, gi.y + gh.y, gi.z + gh.z, gi.w + gh.w);
                    *(float4*)&st[r * 196 + cbase] = v;
                } else {
                    *(float4*)&st[r * 196 + cbase] = gi;
                    *(float4*)&st2[r * 64 + (cbase - 128)] = gh;
                }
            }
        }
        __syncthreads();

        for (int idx = tid; idx < R * 64; idx += 192) {
            int r = idx >> 6, c = idx & 63;
            float rg = fsig(st[r * 196 + c]);
            float zg = fsig(st[r * 196 + 64 + c]);
            float nv = ftanh(st[r * 196 + 128 + c] + rg * st2[r * 64 + c]);
            float h1o = h1T[c * 10 + r];
            h1T[c * 10 + r] = (1.f - zg) * nv + zg * h1o;
        }
        __syncthreads();

        {
            u64 i00 = 0ull, i01 = 0ull, i10 = 0ull, i11 = 0ull;
            u64 h00 = 0ull, h01 = 0ull, h10 = 0ull, h11 = 0ull;
            for (int k = 0; k < 64; k++) {
                ulonglong2 wi = __ldg(&Wi1u[k * 48 + cq]);
                ulonglong2 wh = __ldg(&Wh1u[k * 48 + cq]);
                float2 a = *(const float2*)&h1T[k * 10 + rb];
                float2 b = *(const float2*)&h2T[k * 10 + rb];
                u64 a0 = pk2(a.x), a1 = pk2(a.y);
                u64 b0 = pk2(b.x), b1 = pk2(b.y);
                i00 = ffma2(a0, wi.x, i00);
                i01 = ffma2(a0, wi.y, i01);
                i10 = ffma2(a1, wi.x, i10);
                i11 = ffma2(a1, wi.y, i11);
                h00 = ffma2(b0, wh.x, h00);
                h01 = ffma2(b0, wh.y, h01);
                h10 = ffma2(b1, wh.x, h10);
                h11 = ffma2(b1, wh.y, h11);
            }
#pragma unroll
            for (int i = 0; i < 2; i++) {
                int r = rb + i;
                float2 ip0 = u2f(i ? i10 : i00);
                float2 ip1 = u2f(i ? i11 : i01);
                float2 hp0 = u2f(i ? h10 : h00);
                float2 hp1 = u2f(i ? h11 : h01);
                float4 gi, gh;
                gi.x = ip0.x + vbih1.x; gi.y = ip0.y + vbih1.y;
                gi.z = ip1.x + vbih1.z; gi.w = ip1.y + vbih1.w;
                gh.x = hp0.x + vbhh1.x; gh.y = hp0.y + vbhh1.y;
                gh.z = hp1.x + vbhh1.z; gh.w = hp1.y + vbhh1.w;
                if (gate < 2) {
                    float4 v = make_float4(gi.x + gh.x, gi.y + gh.y, gi.z + gh.z, gi.w + gh.w);
                    *(float4*)&st[r * 196 + cbase] = v;
                } else {
                    *(float4*)&st[r * 196 + cbase] = gi;
                    *(float4*)&st2[r * 64 + (cbase - 128)] = gh;
                }
            }
        }
        __syncthreads();

        for (int idx = tid; idx < R * 64; idx += 192) {
            int r = idx >> 6, c = idx & 63;
            float rg = fsig(st[r * 196 + c]);
            float zg = fsig(st[r * 196 + 64 + c]);
            float nv = ftanh(st[r * 196 + 128 + c] + rg * st2[r * 64 + c]);
            float h2o = h2T[c * 10 + r];
            h2T[c * 10 + r] = (1.f - zg) * nv + zg * h2o;
        }
    }
    __syncthreads();

    // head MLP: 128 threads, 2 row-groups of 4
    if (tid < 128) {
        int j = tid & 63, rh = tid >> 6;
#pragma unroll
        for (int rr = 0; rr < 4; rr++) {
            int r = rh * 4 + rr;
            float a = __ldg(&pb1[j]);
            for (int k = 0; k < 64; k++) a += h2T[k * 10 + r] * __ldg(&pW1[k * 64 + j]);
            st[r * 68 + j] = fmaxf(a, 0.f);
        }
    }
    __syncthreads();
    if (tid < 80) {
        int r = tid / 10, o = tid % 10;
        float a = __ldg(&pb2[o]);
        for (int k = 0; k < 64; k++) a += st[r * 68 + k] * __ldg(&pW2[k * 10 + o]);
        out[(rowbase + r) * 10 + o] = a;
    }
}

// -------------------- launch ------------------------------------------------------
extern "C" void kernel_launch(void* const* d_in, const int* in_sizes, int n_in,
                              void* d_out, int out_size) {
    const float* x    = (const float*)d_in[0];
    const int*   ei   = (const int*)  d_in[1];
    const float* W1   = (const float*)d_in[3];
    const float* as1  = (const float*)d_in[4];
    const float* ad1  = (const float*)d_in[5];
    const float* b1   = (const float*)d_in[6];
    const float* W2   = (const float*)d_in[7];
    const float* as2  = (const float*)d_in[8];
    const float* ad2  = (const float*)d_in[9];
    const float* b2   = (const float*)d_in[10];
    const float* Wih0 = (const float*)d_in[13];
    const float* Whh0 = (const float*)d_in[14];
    const float* bih0 = (const float*)d_in[15];
    const float* bhh0 = (const float*)d_in[16];
    const float* Wih1 = (const float*)d_in[17];
    const float* Whh1 = (const float*)d_in[18];
    const float* bih1 = (const float*)d_in[19];
    const float* bhh1 = (const float*)d_in[20];
    const float* pW1  = (const float*)d_in[21];
    const float* pb1  = (const float*)d_in[22];
    const float* pW2  = (const float*)d_in[23];
    const float* pb2  = (const float*)d_in[24];
    float* out = (float*)d_out;

    csr_kernel<<<NG + 4, 1024>>>(ei, Whh0, Wih1, Whh1, Wih0);     // 1 (csr + wtrans)
    prologue_kernel<<<GN / 32, 256>>>(x, W1, as1, ad1, 0);        // 2
    aggregate_kernel<<<GN / 8, 256>>>(b1, 1, 0);                  // 3
    prologue_kernel<<<GN / 32, 256>>>(nullptr, W2, as2, ad2, 1);  // 4
    aggregate_kernel<<<GN / 8, 256>>>(b2, 0, 1);                  // 5
    gi_kernel<<<(NT * BN) / 32, 192>>>(bih0);                     // 6
    gru_fused_kernel<<<BN / 8, 192>>>(bhh0, bih1, bhh1, pW1, pb1, pW2, pb2, out); // 7
}